// round 13
// baseline (speedup 1.0000x reference)
#include <cuda_runtime.h>
#include <cuda_fp16.h>
#include <stdint.h>
#include <math.h>

#define B    128
#define H    1024
#define S    512
#define VOUT 50000
#define VIN  32000

#define NTILE  128
#define KC     64
#define NCH    (H / KC)            // 16 chunks per tile
#define NT     ((VOUT + NTILE - 1) / NTILE)   // 391 tiles
#define GRID   148

#define NTHREADS 640               // warps 0-15 consumers, 16-19 producers

// smem stage = 2 tiles (XH, WH), each 128 rows x 144B (64 fp16 + 16B pad;
// stride 144 = 9*16, gcd(9,32)=1 -> conflict-free ldmatrix in 8-row groups)
#define ROWB    144
#define TILE_B  (128 * ROWB)       // 18432
#define XH      0
#define WH      (1 * TILE_B)
#define STAGE_B (2 * TILE_B)       // 36864
#define NSTAGE  4
#define TILES_OFF 1024
#define RED_OFF  (TILES_OFF + NSTAGE * STAGE_B)   // 148480: float ssum[128]
#define CAN_OFF  (RED_OFF + 512)
#define SMEM_TOTAL (CAN_OFF + 512)                // 149504

// ---------------- persistent device scratch ----------------------------------
// g_winner: winner+1 encoding, 0 = none. atomicMax idempotent across calls,
// zero-init at module load => never needs resetting.
__device__ float        g_inpdist[B * VIN];
__device__ int          g_winner[VOUT];
__device__ int          g_cancopy[B];
__device__ float        g_expsum[B];
__device__ float        g_pl[2 * B];
__device__ __half       g_xh[B * H];

__device__ __forceinline__ uint32_t smem_u32(const void* p) {
    uint32_t a;
    asm("{ .reg .u64 t; cvta.to.shared.u64 t, %1; cvt.u32.u64 %0, t; }" : "=r"(a) : "l"(p));
    return a;
}

#define MBARRIER_INIT(addr, cnt) \
    asm volatile("mbarrier.init.shared.b64 [%0], %1;" :: "r"(addr), "r"(cnt) : "memory")
#define MBARRIER_ARRIVE(addr) \
    asm volatile("mbarrier.arrive.shared.b64 _, [%0];" :: "r"(addr) : "memory")
#define MBARRIER_WAIT_PARITY(mbar_addr, phase) do {                                  \
    uint32_t _mb = (uint32_t)(mbar_addr);                                            \
    uint32_t _ph = (uint32_t)(phase);                                                \
    asm volatile(                                                                    \
        "{\n\t.reg .pred P1;\n\t"                                                    \
        "WAIT_LOOP_%=:\n\t"                                                          \
        "mbarrier.try_wait.parity.acquire.cta.shared::cta.b64 P1, [%0], %1, 0x989680;\n\t" \
        "@P1 bra.uni WAIT_DONE_%=;\n\t"                                              \
        "bra.uni WAIT_LOOP_%=;\n\t"                                                  \
        "WAIT_DONE_%=:\n\t}"                                                         \
        :: "r"(_mb), "r"(_ph) : "memory");                                           \
} while (0)

__device__ __forceinline__ void ldm4(uint32_t addr, uint32_t& r0, uint32_t& r1,
                                     uint32_t& r2, uint32_t& r3) {
    asm volatile("ldmatrix.sync.aligned.m8n8.x4.shared.b16 {%0,%1,%2,%3}, [%4];"
                 : "=r"(r0), "=r"(r1), "=r"(r2), "=r"(r3) : "r"(addr));
}
__device__ __forceinline__ uint32_t ldm_addr(uint32_t tile, int base_row, int k16, int lane) {
    int mat = lane >> 3;
    int row = base_row + (lane & 7) + ((mat & 1) << 3);
    int ke  = k16 + ((mat >> 1) << 3);
    return tile + row * ROWB + ke * 2;
}
__device__ __forceinline__ void mma_f16(float* c, const uint32_t* a, uint32_t b0, uint32_t b1) {
    asm volatile(
        "mma.sync.aligned.m16n8k16.row.col.f32.f16.f16.f32 "
        "{%0,%1,%2,%3}, {%4,%5,%6,%7}, {%8,%9}, {%0,%1,%2,%3};"
        : "+f"(c[0]), "+f"(c[1]), "+f"(c[2]), "+f"(c[3])
        : "r"(a[0]), "r"(a[1]), "r"(a[2]), "r"(a[3]), "r"(b0), "r"(b1));
}

// ---------------- K0: x -> fp16 + winner + expsum clear ----------------------
__global__ __launch_bounds__(256) void k_prep(const float* __restrict__ x,
                                              const int* __restrict__ inp_to_act) {
    int i = blockIdx.x * blockDim.x + threadIdx.x;   // 32768 threads
    if (i < B * H / 4) {
        float4 v = ((const float4*)x)[i];
        unsigned h0 = (unsigned)__half_as_ushort(__float2half_rn(v.x));
        unsigned h1 = (unsigned)__half_as_ushort(__float2half_rn(v.y));
        unsigned h2 = (unsigned)__half_as_ushort(__float2half_rn(v.z));
        unsigned h3 = (unsigned)__half_as_ushort(__float2half_rn(v.w));
        ((uint2*)g_xh)[i] = make_uint2(h0 | (h1 << 16), h2 | (h3 << 16));
    }
    if (i < VIN) atomicMax(&g_winner[inp_to_act[i]], i + 1);   // winner+1 encoding
    if (i < B) g_expsum[i] = 0.0f;
}

// ---------------- K1: clear inpdist row + attention softmax + scatter --------
__global__ __launch_bounds__(256) void k_attn(const float* __restrict__ attn,
                                              const int*   __restrict__ inptok,
                                              float*       __restrict__ out_attn) {
    int b = blockIdx.x;
    __shared__ float red[256];
    const float* row = attn + b * S;
    float* drow = g_inpdist + (size_t)b * VIN;

    // clear this block's inpdist row (only this block ever writes it)
    for (int j = threadIdx.x; j < VIN / 4; j += 256)
        ((float4*)drow)[j] = make_float4(0.f, 0.f, 0.f, 0.f);

    float mx = -INFINITY;
    for (int s = threadIdx.x; s < S; s += 256) mx = fmaxf(mx, row[s]);
    red[threadIdx.x] = mx; __syncthreads();
    for (int off = 128; off > 0; off >>= 1) {
        if (threadIdx.x < off) red[threadIdx.x] = fmaxf(red[threadIdx.x], red[threadIdx.x + off]);
        __syncthreads();
    }
    mx = red[0]; __syncthreads();

    float sum = 0.0f;
    for (int s = threadIdx.x; s < S; s += 256) sum += __expf(row[s] - mx);
    red[threadIdx.x] = sum; __syncthreads();
    for (int off = 128; off > 0; off >>= 1) {
        if (threadIdx.x < off) red[threadIdx.x] += red[threadIdx.x + off];
        __syncthreads();
    }
    sum = red[0];
    float inv = 1.0f / sum;

    for (int s = threadIdx.x; s < S; s += 256) {
        float p = __expf(row[s] - mx) * inv;
        out_attn[b * S + s] = p;
        atomicAdd(&drow[inptok[b * S + s]], p);
    }
}

// ---------------- K2: cog gate dot products (gemm-independent part) ----------
__global__ void k_pogdot(const float* __restrict__ x,
                         const float* __restrict__ cogW,
                         const float* __restrict__ cogb) {
    int b = blockIdx.x;
    int lane = threadIdx.x;
    float s0 = 0.f, s1 = 0.f;
    for (int k = lane; k < H; k += 32) {
        float xv = x[b * H + k];
        s0 += xv * cogW[k];
        s1 += xv * cogW[H + k];
    }
#pragma unroll
    for (int off = 16; off > 0; off >>= 1) {
        s0 += __shfl_xor_sync(0xFFFFFFFFu, s0, off);
        s1 += __shfl_xor_sync(0xFFFFFFFFu, s1, off);
    }
    if (lane == 0) {
        g_pl[2 * b]     = s0 + cogb[0];
        g_pl[2 * b + 1] = s1 + cogb[1];
    }
}

// ---------------- K3: warp-specialized persistent GEMM + exp epilogue --------
// 16 consumer warps (32x32 tiles) + 4 producer warps; KC=64 per stage.
__global__ __launch_bounds__(NTHREADS, 1) void k_gemm(const float* __restrict__ W,
                                                      const float* __restrict__ bias,
                                                      const float* __restrict__ mask,
                                                      float*       __restrict__ out_e) {
    extern __shared__ char smem[];
    uint32_t sb = smem_u32(smem);
    int t = threadIdx.x;
    int lane = t & 31;
    int wid = t >> 5;
    float* ssum = (float*)(smem + RED_OFF);
    int*   scan = (int*)(smem + CAN_OFF);

    if (t == 0) {
#pragma unroll
        for (int s = 0; s < NSTAGE; s++) {
            MBARRIER_INIT(sb + s * 16,     128);   // full[s]: 128 producer threads
            MBARRIER_INIT(sb + s * 16 + 8, 512);   // empty[s]: 512 consumer threads
        }
    }
    if (t < 128) { ssum[t] = 0.0f; scan[t] = 0; }
    __syncthreads();

    if (t >= 512) {
        // ================= producers (warps 16-19) =================
        int pt = t - 512;               // 0..127
        int sc = 0, ph = 1;
        for (int tile = blockIdx.x; tile < NT; tile += GRID) {
            int n0 = tile * NTILE;
            for (int c = 0; c < NCH; c++) {
                MBARRIER_WAIT_PARITY(sb + sc * 16 + 8, ph);
                uint32_t buf = sb + TILES_OFF + sc * STAGE_B;
                int k0 = c * KC;
                // x tile: 128 rows x 64 fp16; thread pt copies row pt (8 uint4)
                {
                    const uint4* xh4 = (const uint4*)(g_xh + pt * H + k0);
                    uint32_t ro = buf + XH + pt * ROWB;
#pragma unroll
                    for (int j = 0; j < 8; j++) {
                        uint4 v = xh4[j];
                        asm volatile("st.shared.v4.b32 [%0], {%1,%2,%3,%4};"
                                     :: "r"(ro + j * 16),
                                        "r"(v.x), "r"(v.y), "r"(v.z), "r"(v.w) : "memory");
                    }
                }
                // W tile: 128 rows x 64 fp32 -> fp16; 2048 float4 over 128 threads
#pragma unroll
                for (int i = 0; i < 16; i++) {
                    int g = pt + i * 128;
                    int row = g >> 4, k4 = (g & 15) << 2;
                    int nb = n0 + row;
                    float4 wv = (nb < VOUT)
                        ? *(const float4*)(W + (size_t)nb * H + k0 + k4)
                        : make_float4(0.f, 0.f, 0.f, 0.f);
                    unsigned h0 = (unsigned)__half_as_ushort(__float2half_rn(wv.x));
                    unsigned h1 = (unsigned)__half_as_ushort(__float2half_rn(wv.y));
                    unsigned h2 = (unsigned)__half_as_ushort(__float2half_rn(wv.z));
                    unsigned h3 = (unsigned)__half_as_ushort(__float2half_rn(wv.w));
                    unsigned a = h0 | (h1 << 16), b = h2 | (h3 << 16);
                    asm volatile("st.shared.v2.b32 [%0], {%1,%2};"
                                 :: "r"(buf + WH + row * ROWB + k4 * 2),
                                    "r"(a), "r"(b) : "memory");
                }
                MBARRIER_ARRIVE(sb + sc * 16);
                if (++sc == NSTAGE) { sc = 0; ph ^= 1; }
            }
        }
    } else {
        // ================= consumers (warps 0-15, 32x32 tiles) =================
        int wm = (wid >> 2) * 32;   // 0,32,64,96
        int wn = (wid & 3) * 32;    // 0,32,64,96
        int sc = 0, ph = 0;

        for (int tile = blockIdx.x; tile < NT; tile += GRID) {
            int n0 = tile * NTILE;
            float acc[2][4][4];
#pragma unroll
            for (int mi = 0; mi < 2; mi++)
#pragma unroll
                for (int ni = 0; ni < 4; ni++)
#pragma unroll
                    for (int r = 0; r < 4; r++) acc[mi][ni][r] = 0.0f;

            for (int c = 0; c < NCH; c++) {
                MBARRIER_WAIT_PARITY(sb + sc * 16, ph);
                uint32_t buf = sb + TILES_OFF + sc * STAGE_B;
#pragma unroll
                for (int k16e = 0; k16e < 4; k16e++) {
                    int k16 = k16e * 16;
                    uint32_t bh[4][2];
                    {
                        uint32_t q0, q1, q2, q3;
                        ldm4(ldm_addr(buf + WH, wn,      k16, lane), q0, q1, q2, q3);
                        bh[0][0] = q0; bh[1][0] = q1; bh[0][1] = q2; bh[1][1] = q3;
                        ldm4(ldm_addr(buf + WH, wn + 16, k16, lane), q0, q1, q2, q3);
                        bh[2][0] = q0; bh[3][0] = q1; bh[2][1] = q2; bh[3][1] = q3;
                    }
                    uint32_t ah[2][4];
#pragma unroll
                    for (int mi = 0; mi < 2; mi++)
                        ldm4(ldm_addr(buf + XH, wm + mi * 16, k16, lane),
                             ah[mi][0], ah[mi][1], ah[mi][2], ah[mi][3]);
#pragma unroll
                    for (int mi = 0; mi < 2; mi++)
#pragma unroll
                        for (int ni = 0; ni < 4; ni++)
                            mma_f16(acc[mi][ni], ah[mi], bh[ni][0], bh[ni][1]);
                }
                MBARRIER_ARRIVE(sb + sc * 16 + 8);
                if (++sc == NSTAGE) { sc = 0; ph ^= 1; }
            }

            // ---- per-tile epilogue: e = exp(acc + bias) * mask ----
#pragma unroll
            for (int mi = 0; mi < 2; mi++) {
#pragma unroll
                for (int half = 0; half < 2; half++) {
                    int m = wm + mi * 16 + (lane >> 2) + half * 8;
                    float psum = 0.0f;
                    int can = 0;
#pragma unroll
                    for (int ni = 0; ni < 4; ni++) {
                        int n = n0 + wn + ni * 8 + ((lane & 3) << 1);
                        if (n < VOUT) {
                            size_t idx = (size_t)m * VOUT + n;
                            float2 om = *(const float2*)(mask + idx);
                            float2 bv = *(const float2*)(bias + n);
                            float e0 = __expf(acc[mi][ni][half * 2 + 0] + bv.x) * om.x;
                            float e1 = __expf(acc[mi][ni][half * 2 + 1] + bv.y) * om.y;
                            *(float2*)(out_e + idx) = make_float2(e0, e1);
                            psum += e0 + e1;
                            if (om.x > 0.0f && n != 0 && g_winner[n] > 0) can = 1;
                            if (om.y > 0.0f && g_winner[n + 1] > 0) can = 1;
                        }
                    }
                    psum += __shfl_xor_sync(0xFFFFFFFFu, psum, 1);
                    psum += __shfl_xor_sync(0xFFFFFFFFu, psum, 2);
                    can |= __shfl_xor_sync(0xFFFFFFFFu, can, 1);
                    can |= __shfl_xor_sync(0xFFFFFFFFu, can, 2);
                    if ((lane & 3) == 0) {
                        atomicAdd(&ssum[m], psum);
                        if (can) scan[m] = 1;
                    }
                }
            }
            asm volatile("bar.sync 1, 512;" ::: "memory");
            if (t < 128) {
                atomicAdd(&g_expsum[t], ssum[t]);
                if (scan[t]) g_cancopy[t] = 1;
                ssum[t] = 0.0f;
                scan[t] = 0;
            }
            asm volatile("bar.sync 1, 512;" ::: "memory");
        }
    }
}

// ---------------- K4: normalize + combine + log + pog ------------------------
#define NORMSEG 25    // VOUT/25 = 2000 per segment, even
__global__ __launch_bounds__(256) void k_norm(float* __restrict__ e_gen,
                                              float* __restrict__ out_probs,
                                              float* __restrict__ out_pog) {
    int b = blockIdx.x;
    int seg = blockIdx.y;
    // compute pog gate locally (3 flops, avoids separate kernel)
    float l0 = g_pl[2 * b], l1 = g_pl[2 * b + 1];
    int can = g_cancopy[b];
    float mx = can ? fmaxf(l0, l1) : l0;
    float e0 = __expf(l0 - mx);
    float e1 = can ? __expf(l1 - mx) : 0.0f;
    float pinv = 1.0f / (e0 + e1);
    float pg = e0 * pinv, pc = e1 * pinv;
    if (seg == 0 && threadIdx.x == 0) {
        out_pog[2 * b] = pg;
        out_pog[2 * b + 1] = pc;
    }

    float inv = 1.0f / g_expsum[b];
    const float* dist = g_inpdist + (size_t)b * VIN;
    int n0 = seg * (VOUT / NORMSEG);

    for (int n = n0 + threadIdx.x * 2; n < n0 + (VOUT / NORMSEG); n += 512) {
        size_t idx = (size_t)b * VOUT + n;
        float2 e = *(const float2*)(e_gen + idx);
        int2 w = *(const int2*)(g_winner + n);
        float p0 = e.x * inv, p1 = e.y * inv;
        float ptr0 = (w.x > 0) ? dist[w.x - 1] : 0.0f;
        float ptr1 = (w.y > 0) ? dist[w.y - 1] : 0.0f;
        *(float2*)(out_probs + idx) =
            make_float2(__logf(pg * p0 + pc * ptr0), __logf(pg * p1 + pc * ptr1));
        *(float2*)(e_gen + idx) = make_float2(p0, p1);
    }
}

// ---------------- launch ------------------------------------------------------
extern "C" void kernel_launch(void* const* d_in, const int* in_sizes, int n_in,
                              void* d_out, int out_size) {
    const float* x          = (const float*)d_in[0];
    const int*   inptensor  = (const int*)  d_in[1];
    const float* attn       = (const float*)d_in[2];
    const float* out_mask   = (const float*)d_in[3];
    const float* gen_W      = (const float*)d_in[4];
    const float* gen_b      = (const float*)d_in[5];
    const float* cog_W      = (const float*)d_in[6];
    const float* cog_b      = (const float*)d_in[7];
    const int*   inp_to_act = (const int*)  d_in[8];

    float* out = (float*)d_out;
    float* o_outprobs = out;
    float* o_pog      = out + (size_t)B * VOUT;
    float* o_gen      = o_pog + 2 * B;
    float* o_attn     = o_gen + (size_t)B * VOUT;

    cudaFuncSetAttribute(k_gemm, cudaFuncAttributeMaxDynamicSharedMemorySize, SMEM_TOTAL);

    k_prep<<<128, 256>>>(x, inp_to_act);                          // 0
    k_attn<<<B, 256>>>(attn, inptensor, o_attn);                  // 1
    k_pogdot<<<B, 32>>>(x, cog_W, cog_b);                         // 2
    k_gemm<<<GRID, NTHREADS, SMEM_TOTAL>>>(gen_W, gen_b, out_mask, o_gen);  // 3 <- profiled
    k_norm<<<dim3(B, NORMSEG), 256>>>(o_gen, o_outprobs, o_pog);  // 4
}

// round 14
// speedup vs baseline: 1.2391x; 1.2391x over previous
#include <cuda_runtime.h>
#include <cuda_fp16.h>
#include <stdint.h>
#include <math.h>

#define B    128
#define H    1024
#define S    512
#define VOUT 50000
#define VIN  32000

#define NTILE  128
#define KC     64
#define NCH    (H / KC)            // 16 chunks per tile
#define NT     ((VOUT + NTILE - 1) / NTILE)   // 391 tiles
#define GRID   148

#define NTHREADS 768               // warps 0-15 consumers, 16-23 producers

// smem stage = 2 tiles (XH, WH), each 128 rows x 144B (64 fp16 + 16B pad;
// stride 144 = 9*16, gcd(9,32)=1 -> conflict-free ldmatrix in 8-row groups)
#define ROWB    144
#define TILE_B  (128 * ROWB)       // 18432
#define XH      0
#define WH      (1 * TILE_B)
#define STAGE_B (2 * TILE_B)       // 36864
#define NSTAGE  3
#define TILES_OFF 1024
#define RED_OFF  (TILES_OFF + NSTAGE * STAGE_B)   // 111616: float ssum[128]
#define CAN_OFF  (RED_OFF + 512)
#define SMEM_TOTAL (CAN_OFF + 512)                // 112640

// ---------------- persistent device scratch ----------------------------------
// g_winner: winner+1 encoding, 0 = none. atomicMax idempotent across calls,
// zero-init at module load => never needs resetting.
__device__ float        g_inpdist[B * VIN];
__device__ int          g_winner[VOUT];
__device__ int          g_cancopy[B];
__device__ float        g_expsum[B];
__device__ float        g_pl[2 * B];
__device__ __half       g_xh[B * H];

__device__ __forceinline__ uint32_t smem_u32(const void* p) {
    uint32_t a;
    asm("{ .reg .u64 t; cvta.to.shared.u64 t, %1; cvt.u32.u64 %0, t; }" : "=r"(a) : "l"(p));
    return a;
}

#define MBARRIER_INIT(addr, cnt) \
    asm volatile("mbarrier.init.shared.b64 [%0], %1;" :: "r"(addr), "r"(cnt) : "memory")
#define MBARRIER_ARRIVE(addr) \
    asm volatile("mbarrier.arrive.shared.b64 _, [%0];" :: "r"(addr) : "memory")
#define MBARRIER_WAIT_PARITY(mbar_addr, phase) do {                                  \
    uint32_t _mb = (uint32_t)(mbar_addr);                                            \
    uint32_t _ph = (uint32_t)(phase);                                                \
    asm volatile(                                                                    \
        "{\n\t.reg .pred P1;\n\t"                                                    \
        "WAIT_LOOP_%=:\n\t"                                                          \
        "mbarrier.try_wait.parity.acquire.cta.shared::cta.b64 P1, [%0], %1, 0x989680;\n\t" \
        "@P1 bra.uni WAIT_DONE_%=;\n\t"                                              \
        "bra.uni WAIT_LOOP_%=;\n\t"                                                  \
        "WAIT_DONE_%=:\n\t}"                                                         \
        :: "r"(_mb), "r"(_ph) : "memory");                                           \
} while (0)

__device__ __forceinline__ void ldm4(uint32_t addr, uint32_t& r0, uint32_t& r1,
                                     uint32_t& r2, uint32_t& r3) {
    asm volatile("ldmatrix.sync.aligned.m8n8.x4.shared.b16 {%0,%1,%2,%3}, [%4];"
                 : "=r"(r0), "=r"(r1), "=r"(r2), "=r"(r3) : "r"(addr));
}
__device__ __forceinline__ uint32_t ldm_addr(uint32_t tile, int base_row, int k16, int lane) {
    int mat = lane >> 3;
    int row = base_row + (lane & 7) + ((mat & 1) << 3);
    int ke  = k16 + ((mat >> 1) << 3);
    return tile + row * ROWB + ke * 2;
}
__device__ __forceinline__ void mma_f16(float* c, const uint32_t* a, uint32_t b0, uint32_t b1) {
    asm volatile(
        "mma.sync.aligned.m16n8k16.row.col.f32.f16.f16.f32 "
        "{%0,%1,%2,%3}, {%4,%5,%6,%7}, {%8,%9}, {%0,%1,%2,%3};"
        : "+f"(c[0]), "+f"(c[1]), "+f"(c[2]), "+f"(c[3])
        : "r"(a[0]), "r"(a[1]), "r"(a[2]), "r"(a[3]), "r"(b0), "r"(b1));
}

// ---------------- K0: x -> fp16 + winner + expsum clear ----------------------
__global__ __launch_bounds__(256) void k_prep(const float* __restrict__ x,
                                              const int* __restrict__ inp_to_act) {
    int i = blockIdx.x * blockDim.x + threadIdx.x;   // 32768 threads
    if (i < B * H / 4) {
        float4 v = ((const float4*)x)[i];
        unsigned h0 = (unsigned)__half_as_ushort(__float2half_rn(v.x));
        unsigned h1 = (unsigned)__half_as_ushort(__float2half_rn(v.y));
        unsigned h2 = (unsigned)__half_as_ushort(__float2half_rn(v.z));
        unsigned h3 = (unsigned)__half_as_ushort(__float2half_rn(v.w));
        ((uint2*)g_xh)[i] = make_uint2(h0 | (h1 << 16), h2 | (h3 << 16));
    }
    if (i < VIN) atomicMax(&g_winner[inp_to_act[i]], i + 1);   // winner+1 encoding
    if (i < B) g_expsum[i] = 0.0f;
}

// ---------------- K1: clear inpdist row + attention softmax + scatter --------
__global__ __launch_bounds__(256) void k_attn(const float* __restrict__ attn,
                                              const int*   __restrict__ inptok,
                                              float*       __restrict__ out_attn) {
    int b = blockIdx.x;
    __shared__ float red[256];
    const float* row = attn + b * S;
    float* drow = g_inpdist + (size_t)b * VIN;

    // clear this block's inpdist row (only this block ever writes it)
    for (int j = threadIdx.x; j < VIN / 4; j += 256)
        ((float4*)drow)[j] = make_float4(0.f, 0.f, 0.f, 0.f);

    float mx = -INFINITY;
    for (int s = threadIdx.x; s < S; s += 256) mx = fmaxf(mx, row[s]);
    red[threadIdx.x] = mx; __syncthreads();
    for (int off = 128; off > 0; off >>= 1) {
        if (threadIdx.x < off) red[threadIdx.x] = fmaxf(red[threadIdx.x], red[threadIdx.x + off]);
        __syncthreads();
    }
    mx = red[0]; __syncthreads();

    float sum = 0.0f;
    for (int s = threadIdx.x; s < S; s += 256) sum += __expf(row[s] - mx);
    red[threadIdx.x] = sum; __syncthreads();
    for (int off = 128; off > 0; off >>= 1) {
        if (threadIdx.x < off) red[threadIdx.x] += red[threadIdx.x + off];
        __syncthreads();
    }
    sum = red[0];
    float inv = 1.0f / sum;

    for (int s = threadIdx.x; s < S; s += 256) {
        float p = __expf(row[s] - mx) * inv;
        out_attn[b * S + s] = p;
        atomicAdd(&drow[inptok[b * S + s]], p);
    }
}

// ---------------- K2: cog gate dot products (gemm-independent part) ----------
__global__ void k_pogdot(const float* __restrict__ x,
                         const float* __restrict__ cogW,
                         const float* __restrict__ cogb) {
    int b = blockIdx.x;
    int lane = threadIdx.x;
    float s0 = 0.f, s1 = 0.f;
    for (int k = lane; k < H; k += 32) {
        float xv = x[b * H + k];
        s0 += xv * cogW[k];
        s1 += xv * cogW[H + k];
    }
#pragma unroll
    for (int off = 16; off > 0; off >>= 1) {
        s0 += __shfl_xor_sync(0xFFFFFFFFu, s0, off);
        s1 += __shfl_xor_sync(0xFFFFFFFFu, s1, off);
    }
    if (lane == 0) {
        g_pl[2 * b]     = s0 + cogb[0];
        g_pl[2 * b + 1] = s1 + cogb[1];
    }
}

// ---------------- K3: warp-specialized persistent GEMM + exp epilogue --------
// 16 consumer warps (32x32 tiles) + 8 producer warps; KC=64 per stage. (R12 config)
__global__ __launch_bounds__(NTHREADS, 1) void k_gemm(const float* __restrict__ W,
                                                      const float* __restrict__ bias,
                                                      const float* __restrict__ mask,
                                                      float*       __restrict__ out_e) {
    extern __shared__ char smem[];
    uint32_t sb = smem_u32(smem);
    int t = threadIdx.x;
    int lane = t & 31;
    int wid = t >> 5;
    float* ssum = (float*)(smem + RED_OFF);
    int*   scan = (int*)(smem + CAN_OFF);

    if (t == 0) {
#pragma unroll
        for (int s = 0; s < NSTAGE; s++) {
            MBARRIER_INIT(sb + s * 16,     256);   // full[s]: 256 producer threads
            MBARRIER_INIT(sb + s * 16 + 8, 512);   // empty[s]: 512 consumer threads
        }
    }
    if (t < 128) { ssum[t] = 0.0f; scan[t] = 0; }
    __syncthreads();

    if (t >= 512) {
        // ================= producers (warps 16-23) =================
        int pt = t - 512;               // 0..255
        int xrow  = pt & 127;           // x row
        int xhalf = pt >> 7;            // 0/1: which 32-col half
        int sc = 0, ph = 1;
        for (int tile = blockIdx.x; tile < NT; tile += GRID) {
            int n0 = tile * NTILE;
            for (int c = 0; c < NCH; c++) {
                MBARRIER_WAIT_PARITY(sb + sc * 16 + 8, ph);
                uint32_t buf = sb + TILES_OFF + sc * STAGE_B;
                int k0 = c * KC;
                // x tile: 128 rows x 64 fp16; 2 threads per row
                {
                    const uint4* xh4 = (const uint4*)(g_xh + xrow * H + k0 + xhalf * 32);
                    uint32_t ro = buf + XH + xrow * ROWB + xhalf * 64;
#pragma unroll
                    for (int j = 0; j < 4; j++) {
                        uint4 v = xh4[j];
                        asm volatile("st.shared.v4.b32 [%0], {%1,%2,%3,%4};"
                                     :: "r"(ro + j * 16),
                                        "r"(v.x), "r"(v.y), "r"(v.z), "r"(v.w) : "memory");
                    }
                }
                // W tile: 128 rows x 64 fp32 -> fp16; 2048 float4 over 256 threads
#pragma unroll
                for (int i = 0; i < 8; i++) {
                    int g = pt + i * 256;
                    int row = g >> 4, k4 = (g & 15) << 2;
                    int nb = n0 + row;
                    float4 wv = (nb < VOUT)
                        ? *(const float4*)(W + (size_t)nb * H + k0 + k4)
                        : make_float4(0.f, 0.f, 0.f, 0.f);
                    unsigned h0 = (unsigned)__half_as_ushort(__float2half_rn(wv.x));
                    unsigned h1 = (unsigned)__half_as_ushort(__float2half_rn(wv.y));
                    unsigned h2 = (unsigned)__half_as_ushort(__float2half_rn(wv.z));
                    unsigned h3 = (unsigned)__half_as_ushort(__float2half_rn(wv.w));
                    unsigned a = h0 | (h1 << 16), b = h2 | (h3 << 16);
                    asm volatile("st.shared.v2.b32 [%0], {%1,%2};"
                                 :: "r"(buf + WH + row * ROWB + k4 * 2),
                                    "r"(a), "r"(b) : "memory");
                }
                MBARRIER_ARRIVE(sb + sc * 16);
                if (++sc == NSTAGE) { sc = 0; ph ^= 1; }
            }
        }
    } else {
        // ================= consumers (warps 0-15, 32x32 tiles) =================
        int wm = (wid >> 2) * 32;   // 0,32,64,96
        int wn = (wid & 3) * 32;    // 0,32,64,96
        int sc = 0, ph = 0;

        for (int tile = blockIdx.x; tile < NT; tile += GRID) {
            int n0 = tile * NTILE;
            float acc[2][4][4];
#pragma unroll
            for (int mi = 0; mi < 2; mi++)
#pragma unroll
                for (int ni = 0; ni < 4; ni++)
#pragma unroll
                    for (int r = 0; r < 4; r++) acc[mi][ni][r] = 0.0f;

            for (int c = 0; c < NCH; c++) {
                MBARRIER_WAIT_PARITY(sb + sc * 16, ph);
                uint32_t buf = sb + TILES_OFF + sc * STAGE_B;
#pragma unroll
                for (int k16e = 0; k16e < 4; k16e++) {
                    int k16 = k16e * 16;
                    uint32_t bh[4][2];
                    {
                        uint32_t q0, q1, q2, q3;
                        ldm4(ldm_addr(buf + WH, wn,      k16, lane), q0, q1, q2, q3);
                        bh[0][0] = q0; bh[1][0] = q1; bh[0][1] = q2; bh[1][1] = q3;
                        ldm4(ldm_addr(buf + WH, wn + 16, k16, lane), q0, q1, q2, q3);
                        bh[2][0] = q0; bh[3][0] = q1; bh[2][1] = q2; bh[3][1] = q3;
                    }
                    uint32_t ah[2][4];
#pragma unroll
                    for (int mi = 0; mi < 2; mi++)
                        ldm4(ldm_addr(buf + XH, wm + mi * 16, k16, lane),
                             ah[mi][0], ah[mi][1], ah[mi][2], ah[mi][3]);
#pragma unroll
                    for (int mi = 0; mi < 2; mi++)
#pragma unroll
                        for (int ni = 0; ni < 4; ni++)
                            mma_f16(acc[mi][ni], ah[mi], bh[ni][0], bh[ni][1]);
                }
                MBARRIER_ARRIVE(sb + sc * 16 + 8);
                if (++sc == NSTAGE) { sc = 0; ph ^= 1; }
            }

            // ---- per-tile epilogue: e = exp(acc + bias) * mask ----
#pragma unroll
            for (int mi = 0; mi < 2; mi++) {
#pragma unroll
                for (int half = 0; half < 2; half++) {
                    int m = wm + mi * 16 + (lane >> 2) + half * 8;
                    float psum = 0.0f;
                    int can = 0;
#pragma unroll
                    for (int ni = 0; ni < 4; ni++) {
                        int n = n0 + wn + ni * 8 + ((lane & 3) << 1);
                        if (n < VOUT) {
                            size_t idx = (size_t)m * VOUT + n;
                            float2 om = *(const float2*)(mask + idx);
                            float2 bv = *(const float2*)(bias + n);
                            float e0 = __expf(acc[mi][ni][half * 2 + 0] + bv.x) * om.x;
                            float e1 = __expf(acc[mi][ni][half * 2 + 1] + bv.y) * om.y;
                            *(float2*)(out_e + idx) = make_float2(e0, e1);
                            psum += e0 + e1;
                            if (om.x > 0.0f && n != 0 && g_winner[n] > 0) can = 1;
                            if (om.y > 0.0f && g_winner[n + 1] > 0) can = 1;
                        }
                    }
                    psum += __shfl_xor_sync(0xFFFFFFFFu, psum, 1);
                    psum += __shfl_xor_sync(0xFFFFFFFFu, psum, 2);
                    can |= __shfl_xor_sync(0xFFFFFFFFu, can, 1);
                    can |= __shfl_xor_sync(0xFFFFFFFFu, can, 2);
                    if ((lane & 3) == 0) {
                        atomicAdd(&ssum[m], psum);
                        if (can) scan[m] = 1;
                    }
                }
            }
            asm volatile("bar.sync 1, 512;" ::: "memory");
            if (t < 128) {
                atomicAdd(&g_expsum[t], ssum[t]);
                if (scan[t]) g_cancopy[t] = 1;
                ssum[t] = 0.0f;
                scan[t] = 0;
            }
            asm volatile("bar.sync 1, 512;" ::: "memory");
        }
    }
}

// ---------------- K4: normalize + combine + log + pog ------------------------
#define NORMSEG 25    // VOUT/25 = 2000 per segment, even
__global__ __launch_bounds__(256) void k_norm(float* __restrict__ e_gen,
                                              float* __restrict__ out_probs,
                                              float* __restrict__ out_pog) {
    int b = blockIdx.x;
    int seg = blockIdx.y;
    // compute pog gate locally (3 flops, avoids separate kernel)
    float l0 = g_pl[2 * b], l1 = g_pl[2 * b + 1];
    int can = g_cancopy[b];
    float mx = can ? fmaxf(l0, l1) : l0;
    float e0 = __expf(l0 - mx);
    float e1 = can ? __expf(l1 - mx) : 0.0f;
    float pinv = 1.0f / (e0 + e1);
    float pg = e0 * pinv, pc = e1 * pinv;
    if (seg == 0 && threadIdx.x == 0) {
        out_pog[2 * b] = pg;
        out_pog[2 * b + 1] = pc;
    }

    float inv = 1.0f / g_expsum[b];
    const float* dist = g_inpdist + (size_t)b * VIN;
    int n0 = seg * (VOUT / NORMSEG);

    for (int n = n0 + threadIdx.x * 2; n < n0 + (VOUT / NORMSEG); n += 512) {
        size_t idx = (size_t)b * VOUT + n;
        float2 e = *(const float2*)(e_gen + idx);
        int2 w = *(const int2*)(g_winner + n);
        float p0 = e.x * inv, p1 = e.y * inv;
        float ptr0 = (w.x > 0) ? dist[w.x - 1] : 0.0f;
        float ptr1 = (w.y > 0) ? dist[w.y - 1] : 0.0f;
        *(float2*)(out_probs + idx) =
            make_float2(__logf(pg * p0 + pc * ptr0), __logf(pg * p1 + pc * ptr1));
        *(float2*)(e_gen + idx) = make_float2(p0, p1);
    }
}

// ---------------- launch ------------------------------------------------------
extern "C" void kernel_launch(void* const* d_in, const int* in_sizes, int n_in,
                              void* d_out, int out_size) {
    const float* x          = (const float*)d_in[0];
    const int*   inptensor  = (const int*)  d_in[1];
    const float* attn       = (const float*)d_in[2];
    const float* out_mask   = (const float*)d_in[3];
    const float* gen_W      = (const float*)d_in[4];
    const float* gen_b      = (const float*)d_in[5];
    const float* cog_W      = (const float*)d_in[6];
    const float* cog_b      = (const float*)d_in[7];
    const int*   inp_to_act = (const int*)  d_in[8];

    float* out = (float*)d_out;
    float* o_outprobs = out;
    float* o_pog      = out + (size_t)B * VOUT;
    float* o_gen      = o_pog + 2 * B;
    float* o_attn     = o_gen + (size_t)B * VOUT;

    cudaFuncSetAttribute(k_gemm, cudaFuncAttributeMaxDynamicSharedMemorySize, SMEM_TOTAL);

    k_prep<<<128, 256>>>(x, inp_to_act);                          // 0
    k_attn<<<B, 256>>>(attn, inptensor, o_attn);                  // 1
    k_pogdot<<<B, 32>>>(x, cog_W, cog_b);                         // 2
    k_gemm<<<GRID, NTHREADS, SMEM_TOTAL>>>(gen_W, gen_b, out_mask, o_gen);  // 3 <- profiled
    k_norm<<<dim3(B, NORMSEG), 256>>>(o_gen, o_outprobs, o_pog);  // 4
}

// round 15
// speedup vs baseline: 1.3975x; 1.1278x over previous
#include <cuda_runtime.h>
#include <cuda_fp16.h>
#include <stdint.h>
#include <math.h>

#define B    128
#define H    1024
#define S    512
#define VOUT 50000
#define VIN  32000

#define NTILE  128
#define KC     64
#define NCH    (H / KC)            // 16 chunks per tile
#define NT     ((VOUT + NTILE - 1) / NTILE)   // 391 tiles
#define GRID   148

#define NTHREADS 768               // warps 0-15 consumers, 16-23 producers

// smem stage = 2 tiles (XH, WH), each 128 rows x 144B (64 fp16 + 16B pad;
// stride 144 = 9*16, gcd(9,32)=1 -> conflict-free ldmatrix in 8-row groups)
#define ROWB    144
#define TILE_B  (128 * ROWB)       // 18432
#define XH      0
#define WH      (1 * TILE_B)
#define STAGE_B (2 * TILE_B)       // 36864
#define NSTAGE  4
#define TILES_OFF 1024
#define RED_OFF  (TILES_OFF + NSTAGE * STAGE_B)   // 148480: float ssum[128]
#define CAN_OFF  (RED_OFF + 512)
#define SMEM_TOTAL (CAN_OFF + 512)                // 149504

// ---------------- persistent device scratch ----------------------------------
// g_winner: winner+1 encoding, 0 = none. atomicMax idempotent across calls,
// zero-init at module load => never needs resetting.
__device__ float        g_inpdist[B * VIN];
__device__ int          g_winner[VOUT];
__device__ int          g_cancopy[B];
__device__ float        g_expsum[B];
__device__ float        g_pl[2 * B];
__device__ __half       g_xh[B * H];

__device__ __forceinline__ uint32_t smem_u32(const void* p) {
    uint32_t a;
    asm("{ .reg .u64 t; cvta.to.shared.u64 t, %1; cvt.u32.u64 %0, t; }" : "=r"(a) : "l"(p));
    return a;
}

#define MBARRIER_INIT(addr, cnt) \
    asm volatile("mbarrier.init.shared.b64 [%0], %1;" :: "r"(addr), "r"(cnt) : "memory")
#define MBARRIER_ARRIVE(addr) \
    asm volatile("mbarrier.arrive.shared.b64 _, [%0];" :: "r"(addr) : "memory")
#define MBARRIER_WAIT_PARITY(mbar_addr, phase) do {                                  \
    uint32_t _mb = (uint32_t)(mbar_addr);                                            \
    uint32_t _ph = (uint32_t)(phase);                                                \
    asm volatile(                                                                    \
        "{\n\t.reg .pred P1;\n\t"                                                    \
        "WAIT_LOOP_%=:\n\t"                                                          \
        "mbarrier.try_wait.parity.acquire.cta.shared::cta.b64 P1, [%0], %1, 0x989680;\n\t" \
        "@P1 bra.uni WAIT_DONE_%=;\n\t"                                              \
        "bra.uni WAIT_LOOP_%=;\n\t"                                                  \
        "WAIT_DONE_%=:\n\t}"                                                         \
        :: "r"(_mb), "r"(_ph) : "memory");                                           \
} while (0)

__device__ __forceinline__ void ldm4(uint32_t addr, uint32_t& r0, uint32_t& r1,
                                     uint32_t& r2, uint32_t& r3) {
    asm volatile("ldmatrix.sync.aligned.m8n8.x4.shared.b16 {%0,%1,%2,%3}, [%4];"
                 : "=r"(r0), "=r"(r1), "=r"(r2), "=r"(r3) : "r"(addr));
}
__device__ __forceinline__ uint32_t ldm_addr(uint32_t tile, int base_row, int k16, int lane) {
    int mat = lane >> 3;
    int row = base_row + (lane & 7) + ((mat & 1) << 3);
    int ke  = k16 + ((mat >> 1) << 3);
    return tile + row * ROWB + ke * 2;
}
__device__ __forceinline__ void mma_f16(float* c, const uint32_t* a, uint32_t b0, uint32_t b1) {
    asm volatile(
        "mma.sync.aligned.m16n8k16.row.col.f32.f16.f16.f32 "
        "{%0,%1,%2,%3}, {%4,%5,%6,%7}, {%8,%9}, {%0,%1,%2,%3};"
        : "+f"(c[0]), "+f"(c[1]), "+f"(c[2]), "+f"(c[3])
        : "r"(a[0]), "r"(a[1]), "r"(a[2]), "r"(a[3]), "r"(b0), "r"(b1));
}

// ---------------- K0: x -> fp16 + winner + expsum clear ----------------------
__global__ __launch_bounds__(256) void k_prep(const float* __restrict__ x,
                                              const int* __restrict__ inp_to_act) {
    int i = blockIdx.x * blockDim.x + threadIdx.x;   // 32768 threads
    if (i < B * H / 4) {
        float4 v = ((const float4*)x)[i];
        unsigned h0 = (unsigned)__half_as_ushort(__float2half_rn(v.x));
        unsigned h1 = (unsigned)__half_as_ushort(__float2half_rn(v.y));
        unsigned h2 = (unsigned)__half_as_ushort(__float2half_rn(v.z));
        unsigned h3 = (unsigned)__half_as_ushort(__float2half_rn(v.w));
        ((uint2*)g_xh)[i] = make_uint2(h0 | (h1 << 16), h2 | (h3 << 16));
    }
    if (i < VIN) atomicMax(&g_winner[inp_to_act[i]], i + 1);   // winner+1 encoding
    if (i < B) g_expsum[i] = 0.0f;
}

// ---------------- K1: clear inpdist row + attention softmax + scatter --------
__global__ __launch_bounds__(256) void k_attn(const float* __restrict__ attn,
                                              const int*   __restrict__ inptok,
                                              float*       __restrict__ out_attn) {
    int b = blockIdx.x;
    __shared__ float red[256];
    const float* row = attn + b * S;
    float* drow = g_inpdist + (size_t)b * VIN;

    // clear this block's inpdist row (only this block ever writes it)
    for (int j = threadIdx.x; j < VIN / 4; j += 256)
        ((float4*)drow)[j] = make_float4(0.f, 0.f, 0.f, 0.f);

    float mx = -INFINITY;
    for (int s = threadIdx.x; s < S; s += 256) mx = fmaxf(mx, row[s]);
    red[threadIdx.x] = mx; __syncthreads();
    for (int off = 128; off > 0; off >>= 1) {
        if (threadIdx.x < off) red[threadIdx.x] = fmaxf(red[threadIdx.x], red[threadIdx.x + off]);
        __syncthreads();
    }
    mx = red[0]; __syncthreads();

    float sum = 0.0f;
    for (int s = threadIdx.x; s < S; s += 256) sum += __expf(row[s] - mx);
    red[threadIdx.x] = sum; __syncthreads();
    for (int off = 128; off > 0; off >>= 1) {
        if (threadIdx.x < off) red[threadIdx.x] += red[threadIdx.x + off];
        __syncthreads();
    }
    sum = red[0];
    float inv = 1.0f / sum;

    for (int s = threadIdx.x; s < S; s += 256) {
        float p = __expf(row[s] - mx) * inv;
        out_attn[b * S + s] = p;
        atomicAdd(&drow[inptok[b * S + s]], p);
    }
}

// ---------------- K2: cog gate dot products (gemm-independent part) ----------
__global__ void k_pogdot(const float* __restrict__ x,
                         const float* __restrict__ cogW,
                         const float* __restrict__ cogb) {
    int b = blockIdx.x;
    int lane = threadIdx.x;
    float s0 = 0.f, s1 = 0.f;
    for (int k = lane; k < H; k += 32) {
        float xv = x[b * H + k];
        s0 += xv * cogW[k];
        s1 += xv * cogW[H + k];
    }
#pragma unroll
    for (int off = 16; off > 0; off >>= 1) {
        s0 += __shfl_xor_sync(0xFFFFFFFFu, s0, off);
        s1 += __shfl_xor_sync(0xFFFFFFFFu, s1, off);
    }
    if (lane == 0) {
        g_pl[2 * b]     = s0 + cogb[0];
        g_pl[2 * b + 1] = s1 + cogb[1];
    }
}

// ---------------- K3: warp-specialized persistent GEMM + exp epilogue --------
// 16 consumer warps (32x32 tiles) + 8 producer warps; KC=64 per stage.
// Producer loads are two-phase batched to maximize MLP (DRAM feed).
__global__ __launch_bounds__(NTHREADS, 1) void k_gemm(const float* __restrict__ W,
                                                      const float* __restrict__ bias,
                                                      const float* __restrict__ mask,
                                                      float*       __restrict__ out_e) {
    extern __shared__ char smem[];
    uint32_t sb = smem_u32(smem);
    int t = threadIdx.x;
    int lane = t & 31;
    int wid = t >> 5;
    float* ssum = (float*)(smem + RED_OFF);
    int*   scan = (int*)(smem + CAN_OFF);

    if (t == 0) {
#pragma unroll
        for (int s = 0; s < NSTAGE; s++) {
            MBARRIER_INIT(sb + s * 16,     256);   // full[s]: 256 producer threads
            MBARRIER_INIT(sb + s * 16 + 8, 512);   // empty[s]: 512 consumer threads
        }
    }
    if (t < 128) { ssum[t] = 0.0f; scan[t] = 0; }
    __syncthreads();

    if (t >= 512) {
        // ================= producers (warps 16-23) =================
        int pt = t - 512;               // 0..255
        int xrow  = pt & 127;           // x row
        int xhalf = pt >> 7;            // 0/1: which 32-col half
        int sc = 0, ph = 1;
        for (int tile = blockIdx.x; tile < NT; tile += GRID) {
            int n0 = tile * NTILE;
            for (int c = 0; c < NCH; c++) {
                MBARRIER_WAIT_PARITY(sb + sc * 16 + 8, ph);
                uint32_t buf = sb + TILES_OFF + sc * STAGE_B;
                int k0 = c * KC;

                // Phase 1: batch ALL global loads (max MLP)
                uint4 xv[4];
                {
                    const uint4* xh4 = (const uint4*)(g_xh + xrow * H + k0 + xhalf * 32);
#pragma unroll
                    for (int j = 0; j < 4; j++) xv[j] = xh4[j];
                }
                float4 wv[8];
#pragma unroll
                for (int i = 0; i < 8; i++) {
                    int g = pt + i * 256;
                    int row = g >> 4, k4 = (g & 15) << 2;
                    int nb = n0 + row;
                    wv[i] = (nb < VOUT)
                        ? *(const float4*)(W + (size_t)nb * H + k0 + k4)
                        : make_float4(0.f, 0.f, 0.f, 0.f);
                }

                // Phase 2: stores / converts
                {
                    uint32_t ro = buf + XH + xrow * ROWB + xhalf * 64;
#pragma unroll
                    for (int j = 0; j < 4; j++) {
                        asm volatile("st.shared.v4.b32 [%0], {%1,%2,%3,%4};"
                                     :: "r"(ro + j * 16),
                                        "r"(xv[j].x), "r"(xv[j].y), "r"(xv[j].z), "r"(xv[j].w)
                                     : "memory");
                    }
                }
#pragma unroll
                for (int i = 0; i < 8; i++) {
                    int g = pt + i * 256;
                    int row = g >> 4, k4 = (g & 15) << 2;
                    unsigned h0 = (unsigned)__half_as_ushort(__float2half_rn(wv[i].x));
                    unsigned h1 = (unsigned)__half_as_ushort(__float2half_rn(wv[i].y));
                    unsigned h2 = (unsigned)__half_as_ushort(__float2half_rn(wv[i].z));
                    unsigned h3 = (unsigned)__half_as_ushort(__float2half_rn(wv[i].w));
                    unsigned a = h0 | (h1 << 16), b = h2 | (h3 << 16);
                    asm volatile("st.shared.v2.b32 [%0], {%1,%2};"
                                 :: "r"(buf + WH + row * ROWB + k4 * 2),
                                    "r"(a), "r"(b) : "memory");
                }
                MBARRIER_ARRIVE(sb + sc * 16);
                if (++sc == NSTAGE) { sc = 0; ph ^= 1; }
            }
        }
    } else {
        // ================= consumers (warps 0-15, 32x32 tiles) =================
        int wm = (wid >> 2) * 32;   // 0,32,64,96
        int wn = (wid & 3) * 32;    // 0,32,64,96
        int sc = 0, ph = 0;

        for (int tile = blockIdx.x; tile < NT; tile += GRID) {
            int n0 = tile * NTILE;
            float acc[2][4][4];
#pragma unroll
            for (int mi = 0; mi < 2; mi++)
#pragma unroll
                for (int ni = 0; ni < 4; ni++)
#pragma unroll
                    for (int r = 0; r < 4; r++) acc[mi][ni][r] = 0.0f;

            for (int c = 0; c < NCH; c++) {
                MBARRIER_WAIT_PARITY(sb + sc * 16, ph);
                uint32_t buf = sb + TILES_OFF + sc * STAGE_B;
#pragma unroll
                for (int k16e = 0; k16e < 4; k16e++) {
                    int k16 = k16e * 16;
                    uint32_t bh[4][2];
                    {
                        uint32_t q0, q1, q2, q3;
                        ldm4(ldm_addr(buf + WH, wn,      k16, lane), q0, q1, q2, q3);
                        bh[0][0] = q0; bh[1][0] = q1; bh[0][1] = q2; bh[1][1] = q3;
                        ldm4(ldm_addr(buf + WH, wn + 16, k16, lane), q0, q1, q2, q3);
                        bh[2][0] = q0; bh[3][0] = q1; bh[2][1] = q2; bh[3][1] = q3;
                    }
                    uint32_t ah[2][4];
#pragma unroll
                    for (int mi = 0; mi < 2; mi++)
                        ldm4(ldm_addr(buf + XH, wm + mi * 16, k16, lane),
                             ah[mi][0], ah[mi][1], ah[mi][2], ah[mi][3]);
#pragma unroll
                    for (int mi = 0; mi < 2; mi++)
#pragma unroll
                        for (int ni = 0; ni < 4; ni++)
                            mma_f16(acc[mi][ni], ah[mi], bh[ni][0], bh[ni][1]);
                }
                MBARRIER_ARRIVE(sb + sc * 16 + 8);
                if (++sc == NSTAGE) { sc = 0; ph ^= 1; }
            }

            // ---- per-tile epilogue: e = exp(acc + bias) * mask ----
#pragma unroll
            for (int mi = 0; mi < 2; mi++) {
#pragma unroll
                for (int half = 0; half < 2; half++) {
                    int m = wm + mi * 16 + (lane >> 2) + half * 8;
                    float psum = 0.0f;
                    int can = 0;
#pragma unroll
                    for (int ni = 0; ni < 4; ni++) {
                        int n = n0 + wn + ni * 8 + ((lane & 3) << 1);
                        if (n < VOUT) {
                            size_t idx = (size_t)m * VOUT + n;
                            float2 om = *(const float2*)(mask + idx);
                            float2 bv = *(const float2*)(bias + n);
                            float e0 = __expf(acc[mi][ni][half * 2 + 0] + bv.x) * om.x;
                            float e1 = __expf(acc[mi][ni][half * 2 + 1] + bv.y) * om.y;
                            *(float2*)(out_e + idx) = make_float2(e0, e1);
                            psum += e0 + e1;
                            if (om.x > 0.0f && n != 0 && g_winner[n] > 0) can = 1;
                            if (om.y > 0.0f && g_winner[n + 1] > 0) can = 1;
                        }
                    }
                    psum += __shfl_xor_sync(0xFFFFFFFFu, psum, 1);
                    psum += __shfl_xor_sync(0xFFFFFFFFu, psum, 2);
                    can |= __shfl_xor_sync(0xFFFFFFFFu, can, 1);
                    can |= __shfl_xor_sync(0xFFFFFFFFu, can, 2);
                    if ((lane & 3) == 0) {
                        atomicAdd(&ssum[m], psum);
                        if (can) scan[m] = 1;
                    }
                }
            }
            asm volatile("bar.sync 1, 512;" ::: "memory");
            if (t < 128) {
                atomicAdd(&g_expsum[t], ssum[t]);
                if (scan[t]) g_cancopy[t] = 1;
                ssum[t] = 0.0f;
                scan[t] = 0;
            }
            asm volatile("bar.sync 1, 512;" ::: "memory");
        }
    }
}

// ---------------- K4: normalize + combine + log + pog ------------------------
#define NORMSEG 25    // VOUT/25 = 2000 per segment, even
__global__ __launch_bounds__(256) void k_norm(float* __restrict__ e_gen,
                                              float* __restrict__ out_probs,
                                              float* __restrict__ out_pog) {
    int b = blockIdx.x;
    int seg = blockIdx.y;
    // compute pog gate locally (3 flops, avoids separate kernel)
    float l0 = g_pl[2 * b], l1 = g_pl[2 * b + 1];
    int can = g_cancopy[b];
    float mx = can ? fmaxf(l0, l1) : l0;
    float e0 = __expf(l0 - mx);
    float e1 = can ? __expf(l1 - mx) : 0.0f;
    float pinv = 1.0f / (e0 + e1);
    float pg = e0 * pinv, pc = e1 * pinv;
    if (seg == 0 && threadIdx.x == 0) {
        out_pog[2 * b] = pg;
        out_pog[2 * b + 1] = pc;
    }

    float inv = 1.0f / g_expsum[b];
    const float* dist = g_inpdist + (size_t)b * VIN;
    int n0 = seg * (VOUT / NORMSEG);

    for (int n = n0 + threadIdx.x * 2; n < n0 + (VOUT / NORMSEG); n += 512) {
        size_t idx = (size_t)b * VOUT + n;
        float2 e = *(const float2*)(e_gen + idx);
        int2 w = *(const int2*)(g_winner + n);
        float p0 = e.x * inv, p1 = e.y * inv;
        float ptr0 = (w.x > 0) ? dist[w.x - 1] : 0.0f;
        float ptr1 = (w.y > 0) ? dist[w.y - 1] : 0.0f;
        *(float2*)(out_probs + idx) =
            make_float2(__logf(pg * p0 + pc * ptr0), __logf(pg * p1 + pc * ptr1));
        *(float2*)(e_gen + idx) = make_float2(p0, p1);
    }
}

// ---------------- launch ------------------------------------------------------
extern "C" void kernel_launch(void* const* d_in, const int* in_sizes, int n_in,
                              void* d_out, int out_size) {
    const float* x          = (const float*)d_in[0];
    const int*   inptensor  = (const int*)  d_in[1];
    const float* attn       = (const float*)d_in[2];
    const float* out_mask   = (const float*)d_in[3];
    const float* gen_W      = (const float*)d_in[4];
    const float* gen_b      = (const float*)d_in[5];
    const float* cog_W      = (const float*)d_in[6];
    const float* cog_b      = (const float*)d_in[7];
    const int*   inp_to_act = (const int*)  d_in[8];

    float* out = (float*)d_out;
    float* o_outprobs = out;
    float* o_pog      = out + (size_t)B * VOUT;
    float* o_gen      = o_pog + 2 * B;
    float* o_attn     = o_gen + (size_t)B * VOUT;

    cudaFuncSetAttribute(k_gemm, cudaFuncAttributeMaxDynamicSharedMemorySize, SMEM_TOTAL);

    k_prep<<<128, 256>>>(x, inp_to_act);                          // 0
    k_attn<<<B, 256>>>(attn, inptensor, o_attn);                  // 1
    k_pogdot<<<B, 32>>>(x, cog_W, cog_b);                         // 2
    k_gemm<<<GRID, NTHREADS, SMEM_TOTAL>>>(gen_W, gen_b, out_mask, o_gen);  // 3 <- profiled
    k_norm<<<dim3(B, NORMSEG), 256>>>(o_gen, o_outprobs, o_pog);  // 4
}

// round 16
// speedup vs baseline: 1.4166x; 1.0137x over previous
#include <cuda_runtime.h>
#include <cuda_fp16.h>
#include <stdint.h>
#include <math.h>

#define B    128
#define H    1024
#define S    512
#define VOUT 50000
#define VIN  32000

#define NTILE  128
#define KC     64
#define NCH    (H / KC)            // 16 chunks per tile
#define NT     ((VOUT + NTILE - 1) / NTILE)   // 391 tiles
#define GRID   148

#define NTHREADS 768               // warps 0-15 consumers, 16-23 producers

// smem stage = 2 tiles (XH, WH), each 128 rows x 144B (64 fp16 + 16B pad;
// stride 144 = 9*16, gcd(9,32)=1 -> conflict-free ldmatrix in 8-row groups)
#define ROWB    144
#define TILE_B  (128 * ROWB)       // 18432
#define XH      0
#define WH      (1 * TILE_B)
#define STAGE_B (2 * TILE_B)       // 36864
#define NSTAGE  4
#define TILES_OFF 1024
#define RED_OFF  (TILES_OFF + NSTAGE * STAGE_B)   // 148480: float ssum[128]
#define CAN_OFF  (RED_OFF + 512)
#define SMEM_TOTAL (CAN_OFF + 512)                // 149504

// ---------------- persistent device scratch ----------------------------------
// g_winner: winner+1 encoding, 0 = none. atomicMax idempotent across calls,
// zero-init at module load => never needs resetting.
__device__ float        g_inpdist[B * VIN];
__device__ int          g_winner[VOUT];
__device__ int          g_cancopy[B];
__device__ float        g_expsum[B];
__device__ float        g_pl[2 * B];
__device__ __half       g_xh[B * H];

__device__ __forceinline__ uint32_t smem_u32(const void* p) {
    uint32_t a;
    asm("{ .reg .u64 t; cvta.to.shared.u64 t, %1; cvt.u32.u64 %0, t; }" : "=r"(a) : "l"(p));
    return a;
}

#define MBARRIER_INIT(addr, cnt) \
    asm volatile("mbarrier.init.shared.b64 [%0], %1;" :: "r"(addr), "r"(cnt) : "memory")
#define MBARRIER_ARRIVE(addr) \
    asm volatile("mbarrier.arrive.shared.b64 _, [%0];" :: "r"(addr) : "memory")
#define MBARRIER_WAIT_PARITY(mbar_addr, phase) do {                                  \
    uint32_t _mb = (uint32_t)(mbar_addr);                                            \
    uint32_t _ph = (uint32_t)(phase);                                                \
    asm volatile(                                                                    \
        "{\n\t.reg .pred P1;\n\t"                                                    \
        "WAIT_LOOP_%=:\n\t"                                                          \
        "mbarrier.try_wait.parity.acquire.cta.shared::cta.b64 P1, [%0], %1, 0x989680;\n\t" \
        "@P1 bra.uni WAIT_DONE_%=;\n\t"                                              \
        "bra.uni WAIT_LOOP_%=;\n\t"                                                  \
        "WAIT_DONE_%=:\n\t}"                                                         \
        :: "r"(_mb), "r"(_ph) : "memory");                                           \
} while (0)

__device__ __forceinline__ void ldm4(uint32_t addr, uint32_t& r0, uint32_t& r1,
                                     uint32_t& r2, uint32_t& r3) {
    asm volatile("ldmatrix.sync.aligned.m8n8.x4.shared.b16 {%0,%1,%2,%3}, [%4];"
                 : "=r"(r0), "=r"(r1), "=r"(r2), "=r"(r3) : "r"(addr));
}
__device__ __forceinline__ uint32_t ldm_addr(uint32_t tile, int base_row, int k16, int lane) {
    int mat = lane >> 3;
    int row = base_row + (lane & 7) + ((mat & 1) << 3);
    int ke  = k16 + ((mat >> 1) << 3);
    return tile + row * ROWB + ke * 2;
}
__device__ __forceinline__ void mma_f16(float* c, const uint32_t* a, uint32_t b0, uint32_t b1) {
    asm volatile(
        "mma.sync.aligned.m16n8k16.row.col.f32.f16.f16.f32 "
        "{%0,%1,%2,%3}, {%4,%5,%6,%7}, {%8,%9}, {%0,%1,%2,%3};"
        : "+f"(c[0]), "+f"(c[1]), "+f"(c[2]), "+f"(c[3])
        : "r"(a[0]), "r"(a[1]), "r"(a[2]), "r"(a[3]), "r"(b0), "r"(b1));
}

// ---------------- K0: x -> fp16 + winner + expsum clear ----------------------
__global__ __launch_bounds__(256) void k_prep(const float* __restrict__ x,
                                              const int* __restrict__ inp_to_act) {
    int i = blockIdx.x * blockDim.x + threadIdx.x;   // 32768 threads
    if (i < B * H / 4) {
        float4 v = ((const float4*)x)[i];
        unsigned h0 = (unsigned)__half_as_ushort(__float2half_rn(v.x));
        unsigned h1 = (unsigned)__half_as_ushort(__float2half_rn(v.y));
        unsigned h2 = (unsigned)__half_as_ushort(__float2half_rn(v.z));
        unsigned h3 = (unsigned)__half_as_ushort(__float2half_rn(v.w));
        ((uint2*)g_xh)[i] = make_uint2(h0 | (h1 << 16), h2 | (h3 << 16));
    }
    if (i < VIN) atomicMax(&g_winner[inp_to_act[i]], i + 1);   // winner+1 encoding
    if (i < B) g_expsum[i] = 0.0f;
}

// ---------------- K1: clear inpdist row + attention softmax + scatter --------
__global__ __launch_bounds__(256) void k_attn(const float* __restrict__ attn,
                                              const int*   __restrict__ inptok,
                                              float*       __restrict__ out_attn) {
    int b = blockIdx.x;
    __shared__ float red[256];
    const float* row = attn + b * S;
    float* drow = g_inpdist + (size_t)b * VIN;

    // clear this block's inpdist row (only this block ever writes it)
    for (int j = threadIdx.x; j < VIN / 4; j += 256)
        ((float4*)drow)[j] = make_float4(0.f, 0.f, 0.f, 0.f);

    float mx = -INFINITY;
    for (int s = threadIdx.x; s < S; s += 256) mx = fmaxf(mx, row[s]);
    red[threadIdx.x] = mx; __syncthreads();
    for (int off = 128; off > 0; off >>= 1) {
        if (threadIdx.x < off) red[threadIdx.x] = fmaxf(red[threadIdx.x], red[threadIdx.x + off]);
        __syncthreads();
    }
    mx = red[0]; __syncthreads();

    float sum = 0.0f;
    for (int s = threadIdx.x; s < S; s += 256) sum += __expf(row[s] - mx);
    red[threadIdx.x] = sum; __syncthreads();
    for (int off = 128; off > 0; off >>= 1) {
        if (threadIdx.x < off) red[threadIdx.x] += red[threadIdx.x + off];
        __syncthreads();
    }
    sum = red[0];
    float inv = 1.0f / sum;

    for (int s = threadIdx.x; s < S; s += 256) {
        float p = __expf(row[s] - mx) * inv;
        out_attn[b * S + s] = p;
        atomicAdd(&drow[inptok[b * S + s]], p);
    }
}

// ---------------- K2: cog gate dot products (gemm-independent part) ----------
__global__ void k_pogdot(const float* __restrict__ x,
                         const float* __restrict__ cogW,
                         const float* __restrict__ cogb) {
    int b = blockIdx.x;
    int lane = threadIdx.x;
    float s0 = 0.f, s1 = 0.f;
    for (int k = lane; k < H; k += 32) {
        float xv = x[b * H + k];
        s0 += xv * cogW[k];
        s1 += xv * cogW[H + k];
    }
#pragma unroll
    for (int off = 16; off > 0; off >>= 1) {
        s0 += __shfl_xor_sync(0xFFFFFFFFu, s0, off);
        s1 += __shfl_xor_sync(0xFFFFFFFFu, s1, off);
    }
    if (lane == 0) {
        g_pl[2 * b]     = s0 + cogb[0];
        g_pl[2 * b + 1] = s1 + cogb[1];
    }
}

// ---------------- K3: warp-specialized persistent GEMM + exp epilogue --------
// 16 consumer warps (32x32 tiles) + 8 producer warps; KC=64 per stage.
// Producer loop is ROTATED: next chunk's global loads issue right after this
// chunk's arrive, overlapping DRAM latency with the empty-barrier wait.
__global__ __launch_bounds__(NTHREADS, 1) void k_gemm(const float* __restrict__ W,
                                                      const float* __restrict__ bias,
                                                      const float* __restrict__ mask,
                                                      float*       __restrict__ out_e) {
    extern __shared__ char smem[];
    uint32_t sb = smem_u32(smem);
    int t = threadIdx.x;
    int lane = t & 31;
    int wid = t >> 5;
    float* ssum = (float*)(smem + RED_OFF);
    int*   scan = (int*)(smem + CAN_OFF);

    if (t == 0) {
#pragma unroll
        for (int s = 0; s < NSTAGE; s++) {
            MBARRIER_INIT(sb + s * 16,     256);   // full[s]: 256 producer threads
            MBARRIER_INIT(sb + s * 16 + 8, 512);   // empty[s]: 512 consumer threads
        }
    }
    if (t < 128) { ssum[t] = 0.0f; scan[t] = 0; }
    __syncthreads();

    if (t >= 512) {
        // ================= producers (warps 16-23), rotated loop =============
        int pt = t - 512;               // 0..255
        int xrow  = pt & 127;           // x row
        int xhalf = pt >> 7;            // 0/1: which 32-col half
        int sc = 0, ph = 1;

        int tile = blockIdx.x;
        int c = 0;
        uint4 xv[4];
        float4 wv[8];

        // prologue: load first chunk
        {
            int k0 = c * KC;
            const uint4* xh4 = (const uint4*)(g_xh + xrow * H + k0 + xhalf * 32);
#pragma unroll
            for (int j = 0; j < 4; j++) xv[j] = xh4[j];
#pragma unroll
            for (int i = 0; i < 8; i++) {
                int g = pt + i * 256;
                int row = g >> 4, k4 = (g & 15) << 2;
                int nb = tile * NTILE + row;
                wv[i] = (nb < VOUT)
                    ? *(const float4*)(W + (size_t)nb * H + k0 + k4)
                    : make_float4(0.f, 0.f, 0.f, 0.f);
            }
        }

        while (tile < NT) {
            MBARRIER_WAIT_PARITY(sb + sc * 16 + 8, ph);
            uint32_t buf = sb + TILES_OFF + sc * STAGE_B;

            // store current chunk (regs -> smem)
            {
                uint32_t ro = buf + XH + xrow * ROWB + xhalf * 64;
#pragma unroll
                for (int j = 0; j < 4; j++) {
                    asm volatile("st.shared.v4.b32 [%0], {%1,%2,%3,%4};"
                                 :: "r"(ro + j * 16),
                                    "r"(xv[j].x), "r"(xv[j].y), "r"(xv[j].z), "r"(xv[j].w)
                                 : "memory");
                }
            }
#pragma unroll
            for (int i = 0; i < 8; i++) {
                int g = pt + i * 256;
                int row = g >> 4, k4 = (g & 15) << 2;
                unsigned h0 = (unsigned)__half_as_ushort(__float2half_rn(wv[i].x));
                unsigned h1 = (unsigned)__half_as_ushort(__float2half_rn(wv[i].y));
                unsigned h2 = (unsigned)__half_as_ushort(__float2half_rn(wv[i].z));
                unsigned h3 = (unsigned)__half_as_ushort(__float2half_rn(wv[i].w));
                unsigned a = h0 | (h1 << 16), b = h2 | (h3 << 16);
                asm volatile("st.shared.v2.b32 [%0], {%1,%2};"
                             :: "r"(buf + WH + row * ROWB + k4 * 2),
                                "r"(a), "r"(b) : "memory");
            }
            MBARRIER_ARRIVE(sb + sc * 16);
            if (++sc == NSTAGE) { sc = 0; ph ^= 1; }

            // advance and prefetch next chunk (overlaps next empty-wait)
            if (++c == NCH) { c = 0; tile += GRID; }
            if (tile < NT) {
                int k0 = c * KC;
                const uint4* xh4 = (const uint4*)(g_xh + xrow * H + k0 + xhalf * 32);
#pragma unroll
                for (int j = 0; j < 4; j++) xv[j] = xh4[j];
#pragma unroll
                for (int i = 0; i < 8; i++) {
                    int g = pt + i * 256;
                    int row = g >> 4, k4 = (g & 15) << 2;
                    int nb = tile * NTILE + row;
                    wv[i] = (nb < VOUT)
                        ? *(const float4*)(W + (size_t)nb * H + k0 + k4)
                        : make_float4(0.f, 0.f, 0.f, 0.f);
                }
            }
        }
    } else {
        // ================= consumers (warps 0-15, 32x32 tiles) =================
        int wm = (wid >> 2) * 32;   // 0,32,64,96
        int wn = (wid & 3) * 32;    // 0,32,64,96
        int sc = 0, ph = 0;

        for (int tile = blockIdx.x; tile < NT; tile += GRID) {
            int n0 = tile * NTILE;
            float acc[2][4][4];
#pragma unroll
            for (int mi = 0; mi < 2; mi++)
#pragma unroll
                for (int ni = 0; ni < 4; ni++)
#pragma unroll
                    for (int r = 0; r < 4; r++) acc[mi][ni][r] = 0.0f;

            for (int c = 0; c < NCH; c++) {
                MBARRIER_WAIT_PARITY(sb + sc * 16, ph);
                uint32_t buf = sb + TILES_OFF + sc * STAGE_B;
#pragma unroll
                for (int k16e = 0; k16e < 4; k16e++) {
                    int k16 = k16e * 16;
                    uint32_t bh[4][2];
                    {
                        uint32_t q0, q1, q2, q3;
                        ldm4(ldm_addr(buf + WH, wn,      k16, lane), q0, q1, q2, q3);
                        bh[0][0] = q0; bh[1][0] = q1; bh[0][1] = q2; bh[1][1] = q3;
                        ldm4(ldm_addr(buf + WH, wn + 16, k16, lane), q0, q1, q2, q3);
                        bh[2][0] = q0; bh[3][0] = q1; bh[2][1] = q2; bh[3][1] = q3;
                    }
                    uint32_t ah[2][4];
#pragma unroll
                    for (int mi = 0; mi < 2; mi++)
                        ldm4(ldm_addr(buf + XH, wm + mi * 16, k16, lane),
                             ah[mi][0], ah[mi][1], ah[mi][2], ah[mi][3]);
#pragma unroll
                    for (int mi = 0; mi < 2; mi++)
#pragma unroll
                        for (int ni = 0; ni < 4; ni++)
                            mma_f16(acc[mi][ni], ah[mi], bh[ni][0], bh[ni][1]);
                }
                MBARRIER_ARRIVE(sb + sc * 16 + 8);
                if (++sc == NSTAGE) { sc = 0; ph ^= 1; }
            }

            // ---- per-tile epilogue: e = exp(acc + bias) * mask ----
#pragma unroll
            for (int mi = 0; mi < 2; mi++) {
#pragma unroll
                for (int half = 0; half < 2; half++) {
                    int m = wm + mi * 16 + (lane >> 2) + half * 8;
                    float psum = 0.0f;
                    int can = 0;
#pragma unroll
                    for (int ni = 0; ni < 4; ni++) {
                        int n = n0 + wn + ni * 8 + ((lane & 3) << 1);
                        if (n < VOUT) {
                            size_t idx = (size_t)m * VOUT + n;
                            float2 om = *(const float2*)(mask + idx);
                            float2 bv = *(const float2*)(bias + n);
                            float e0 = __expf(acc[mi][ni][half * 2 + 0] + bv.x) * om.x;
                            float e1 = __expf(acc[mi][ni][half * 2 + 1] + bv.y) * om.y;
                            *(float2*)(out_e + idx) = make_float2(e0, e1);
                            psum += e0 + e1;
                            if (om.x > 0.0f && n != 0 && g_winner[n] > 0) can = 1;
                            if (om.y > 0.0f && g_winner[n + 1] > 0) can = 1;
                        }
                    }
                    psum += __shfl_xor_sync(0xFFFFFFFFu, psum, 1);
                    psum += __shfl_xor_sync(0xFFFFFFFFu, psum, 2);
                    can |= __shfl_xor_sync(0xFFFFFFFFu, can, 1);
                    can |= __shfl_xor_sync(0xFFFFFFFFu, can, 2);
                    if ((lane & 3) == 0) {
                        atomicAdd(&ssum[m], psum);
                        if (can) scan[m] = 1;
                    }
                }
            }
            asm volatile("bar.sync 1, 512;" ::: "memory");
            if (t < 128) {
                atomicAdd(&g_expsum[t], ssum[t]);
                if (scan[t]) g_cancopy[t] = 1;
                ssum[t] = 0.0f;
                scan[t] = 0;
            }
            asm volatile("bar.sync 1, 512;" ::: "memory");
        }
    }
}

// ---------------- K4: normalize + combine + log + pog ------------------------
#define NORMSEG 25    // VOUT/25 = 2000 per segment, even
__global__ __launch_bounds__(256) void k_norm(float* __restrict__ e_gen,
                                              float* __restrict__ out_probs,
                                              float* __restrict__ out_pog) {
    int b = blockIdx.x;
    int seg = blockIdx.y;
    // compute pog gate locally (3 flops, avoids separate kernel)
    float l0 = g_pl[2 * b], l1 = g_pl[2 * b + 1];
    int can = g_cancopy[b];
    float mx = can ? fmaxf(l0, l1) : l0;
    float e0 = __expf(l0 - mx);
    float e1 = can ? __expf(l1 - mx) : 0.0f;
    float pinv = 1.0f / (e0 + e1);
    float pg = e0 * pinv, pc = e1 * pinv;
    if (seg == 0 && threadIdx.x == 0) {
        out_pog[2 * b] = pg;
        out_pog[2 * b + 1] = pc;
    }

    float inv = 1.0f / g_expsum[b];
    const float* dist = g_inpdist + (size_t)b * VIN;
    int n0 = seg * (VOUT / NORMSEG);

    for (int n = n0 + threadIdx.x * 2; n < n0 + (VOUT / NORMSEG); n += 512) {
        size_t idx = (size_t)b * VOUT + n;
        float2 e = *(const float2*)(e_gen + idx);
        int2 w = *(const int2*)(g_winner + n);
        float p0 = e.x * inv, p1 = e.y * inv;
        float ptr0 = (w.x > 0) ? dist[w.x - 1] : 0.0f;
        float ptr1 = (w.y > 0) ? dist[w.y - 1] : 0.0f;
        *(float2*)(out_probs + idx) =
            make_float2(__logf(pg * p0 + pc * ptr0), __logf(pg * p1 + pc * ptr1));
        *(float2*)(e_gen + idx) = make_float2(p0, p1);
    }
}

// ---------------- launch ------------------------------------------------------
extern "C" void kernel_launch(void* const* d_in, const int* in_sizes, int n_in,
                              void* d_out, int out_size) {
    const float* x          = (const float*)d_in[0];
    const int*   inptensor  = (const int*)  d_in[1];
    const float* attn       = (const float*)d_in[2];
    const float* out_mask   = (const float*)d_in[3];
    const float* gen_W      = (const float*)d_in[4];
    const float* gen_b      = (const float*)d_in[5];
    const float* cog_W      = (const float*)d_in[6];
    const float* cog_b      = (const float*)d_in[7];
    const int*   inp_to_act = (const int*)  d_in[8];

    float* out = (float*)d_out;
    float* o_outprobs = out;
    float* o_pog      = out + (size_t)B * VOUT;
    float* o_gen      = o_pog + 2 * B;
    float* o_attn     = o_gen + (size_t)B * VOUT;

    cudaFuncSetAttribute(k_gemm, cudaFuncAttributeMaxDynamicSharedMemorySize, SMEM_TOTAL);

    k_prep<<<128, 256>>>(x, inp_to_act);                          // 0
    k_attn<<<B, 256>>>(attn, inptensor, o_attn);                  // 1
    k_pogdot<<<B, 32>>>(x, cog_W, cog_b);                         // 2
    k_gemm<<<GRID, NTHREADS, SMEM_TOTAL>>>(gen_W, gen_b, out_mask, o_gen);  // 3 <- profiled
    k_norm<<<dim3(B, NORMSEG), 256>>>(o_gen, o_outprobs, o_pog);  // 4
}

// round 17
// speedup vs baseline: 1.4359x; 1.0136x over previous
#include <cuda_runtime.h>
#include <cuda_fp16.h>
#include <stdint.h>
#include <math.h>

#define B    128
#define H    1024
#define S    512
#define VOUT 50000
#define VIN  32000

#define NTILE  128
#define KC     64
#define NCH    (H / KC)            // 16 chunks per tile
#define NT     ((VOUT + NTILE - 1) / NTILE)   // 391 tiles
#define GRID   148

#define NTHREADS 768               // warps 0-15 consumers, 16-23 producers

// smem stage = 2 tiles (XH, WH), each 128 rows x 144B (64 fp16 + 16B pad;
// stride 144 = 9*16, gcd(9,32)=1 -> conflict-free ldmatrix in 8-row groups)
#define ROWB    144
#define TILE_B  (128 * ROWB)       // 18432
#define XH      0
#define WH      (1 * TILE_B)
#define STAGE_B (2 * TILE_B)       // 36864
#define NSTAGE  5
#define TILES_OFF 1024
#define RED_OFF  (TILES_OFF + NSTAGE * STAGE_B)   // 185344: float ssum[128]
#define CAN_OFF  (RED_OFF + 512)
#define SMEM_TOTAL (CAN_OFF + 512)                // 186368

// ---------------- persistent device scratch ----------------------------------
// g_winner: winner+1 encoding, 0 = none. atomicMax idempotent across calls,
// zero-init at module load => never needs resetting.
__device__ float        g_inpdist[B * VIN];
__device__ int          g_winner[VOUT];
__device__ int          g_cancopy[B];
__device__ float        g_expsum[B];
__device__ float        g_pl[2 * B];
__device__ __half       g_xh[B * H];

__device__ __forceinline__ uint32_t smem_u32(const void* p) {
    uint32_t a;
    asm("{ .reg .u64 t; cvta.to.shared.u64 t, %1; cvt.u32.u64 %0, t; }" : "=r"(a) : "l"(p));
    return a;
}

#define MBARRIER_INIT(addr, cnt) \
    asm volatile("mbarrier.init.shared.b64 [%0], %1;" :: "r"(addr), "r"(cnt) : "memory")
#define MBARRIER_ARRIVE(addr) \
    asm volatile("mbarrier.arrive.shared.b64 _, [%0];" :: "r"(addr) : "memory")
#define MBARRIER_WAIT_PARITY(mbar_addr, phase) do {                                  \
    uint32_t _mb = (uint32_t)(mbar_addr);                                            \
    uint32_t _ph = (uint32_t)(phase);                                                \
    asm volatile(                                                                    \
        "{\n\t.reg .pred P1;\n\t"                                                    \
        "WAIT_LOOP_%=:\n\t"                                                          \
        "mbarrier.try_wait.parity.acquire.cta.shared::cta.b64 P1, [%0], %1, 0x989680;\n\t" \
        "@P1 bra.uni WAIT_DONE_%=;\n\t"                                              \
        "bra.uni WAIT_LOOP_%=;\n\t"                                                  \
        "WAIT_DONE_%=:\n\t}"                                                         \
        :: "r"(_mb), "r"(_ph) : "memory");                                           \
} while (0)

#define CP_ASYNC16(smem_dst, gsrc) \
    asm volatile("cp.async.cg.shared.global [%0], [%1], 16;" \
                 :: "r"(smem_dst), "l"(gsrc) : "memory")
#define CP_ASYNC_COMMIT() asm volatile("cp.async.commit_group;" ::: "memory")
#define CP_ASYNC_WAIT0()  asm volatile("cp.async.wait_group 0;" ::: "memory")

__device__ __forceinline__ void ldm4(uint32_t addr, uint32_t& r0, uint32_t& r1,
                                     uint32_t& r2, uint32_t& r3) {
    asm volatile("ldmatrix.sync.aligned.m8n8.x4.shared.b16 {%0,%1,%2,%3}, [%4];"
                 : "=r"(r0), "=r"(r1), "=r"(r2), "=r"(r3) : "r"(addr));
}
__device__ __forceinline__ uint32_t ldm_addr(uint32_t tile, int base_row, int k16, int lane) {
    int mat = lane >> 3;
    int row = base_row + (lane & 7) + ((mat & 1) << 3);
    int ke  = k16 + ((mat >> 1) << 3);
    return tile + row * ROWB + ke * 2;
}
__device__ __forceinline__ void mma_f16(float* c, const uint32_t* a, uint32_t b0, uint32_t b1) {
    asm volatile(
        "mma.sync.aligned.m16n8k16.row.col.f32.f16.f16.f32 "
        "{%0,%1,%2,%3}, {%4,%5,%6,%7}, {%8,%9}, {%0,%1,%2,%3};"
        : "+f"(c[0]), "+f"(c[1]), "+f"(c[2]), "+f"(c[3])
        : "r"(a[0]), "r"(a[1]), "r"(a[2]), "r"(a[3]), "r"(b0), "r"(b1));
}

// ---------------- K0: x -> fp16 + winner + expsum clear ----------------------
__global__ __launch_bounds__(256) void k_prep(const float* __restrict__ x,
                                              const int* __restrict__ inp_to_act) {
    int i = blockIdx.x * blockDim.x + threadIdx.x;   // 32768 threads
    if (i < B * H / 4) {
        float4 v = ((const float4*)x)[i];
        unsigned h0 = (unsigned)__half_as_ushort(__float2half_rn(v.x));
        unsigned h1 = (unsigned)__half_as_ushort(__float2half_rn(v.y));
        unsigned h2 = (unsigned)__half_as_ushort(__float2half_rn(v.z));
        unsigned h3 = (unsigned)__half_as_ushort(__float2half_rn(v.w));
        ((uint2*)g_xh)[i] = make_uint2(h0 | (h1 << 16), h2 | (h3 << 16));
    }
    if (i < VIN) atomicMax(&g_winner[inp_to_act[i]], i + 1);   // winner+1 encoding
    if (i < B) g_expsum[i] = 0.0f;
}

// ---------------- K1: clear inpdist row + attention softmax + scatter --------
__global__ __launch_bounds__(256) void k_attn(const float* __restrict__ attn,
                                              const int*   __restrict__ inptok,
                                              float*       __restrict__ out_attn) {
    int b = blockIdx.x;
    __shared__ float red[256];
    const float* row = attn + b * S;
    float* drow = g_inpdist + (size_t)b * VIN;

    // clear this block's inpdist row (only this block ever writes it)
    for (int j = threadIdx.x; j < VIN / 4; j += 256)
        ((float4*)drow)[j] = make_float4(0.f, 0.f, 0.f, 0.f);

    float mx = -INFINITY;
    for (int s = threadIdx.x; s < S; s += 256) mx = fmaxf(mx, row[s]);
    red[threadIdx.x] = mx; __syncthreads();
    for (int off = 128; off > 0; off >>= 1) {
        if (threadIdx.x < off) red[threadIdx.x] = fmaxf(red[threadIdx.x], red[threadIdx.x + off]);
        __syncthreads();
    }
    mx = red[0]; __syncthreads();

    float sum = 0.0f;
    for (int s = threadIdx.x; s < S; s += 256) sum += __expf(row[s] - mx);
    red[threadIdx.x] = sum; __syncthreads();
    for (int off = 128; off > 0; off >>= 1) {
        if (threadIdx.x < off) red[threadIdx.x] += red[threadIdx.x + off];
        __syncthreads();
    }
    sum = red[0];
    float inv = 1.0f / sum;

    for (int s = threadIdx.x; s < S; s += 256) {
        float p = __expf(row[s] - mx) * inv;
        out_attn[b * S + s] = p;
        atomicAdd(&drow[inptok[b * S + s]], p);
    }
}

// ---------------- K2: cog gate dot products (gemm-independent part) ----------
__global__ void k_pogdot(const float* __restrict__ x,
                         const float* __restrict__ cogW,
                         const float* __restrict__ cogb) {
    int b = blockIdx.x;
    int lane = threadIdx.x;
    float s0 = 0.f, s1 = 0.f;
    for (int k = lane; k < H; k += 32) {
        float xv = x[b * H + k];
        s0 += xv * cogW[k];
        s1 += xv * cogW[H + k];
    }
#pragma unroll
    for (int off = 16; off > 0; off >>= 1) {
        s0 += __shfl_xor_sync(0xFFFFFFFFu, s0, off);
        s1 += __shfl_xor_sync(0xFFFFFFFFu, s1, off);
    }
    if (lane == 0) {
        g_pl[2 * b]     = s0 + cogb[0];
        g_pl[2 * b + 1] = s1 + cogb[1];
    }
}

// ---------------- K3: warp-specialized persistent GEMM + exp epilogue --------
// 16 consumer warps (32x32 tiles) + 8 producer warps; KC=64 per stage.
// W: rotated LDG batch (MLP). x: cp.async pure copy (off the RF path).
__global__ __launch_bounds__(NTHREADS, 1) void k_gemm(const float* __restrict__ W,
                                                      const float* __restrict__ bias,
                                                      const float* __restrict__ mask,
                                                      float*       __restrict__ out_e) {
    extern __shared__ char smem[];
    uint32_t sb = smem_u32(smem);
    int t = threadIdx.x;
    int lane = t & 31;
    int wid = t >> 5;
    float* ssum = (float*)(smem + RED_OFF);
    int*   scan = (int*)(smem + CAN_OFF);

    if (t == 0) {
#pragma unroll
        for (int s = 0; s < NSTAGE; s++) {
            MBARRIER_INIT(sb + s * 16,     256);   // full[s]: 256 producer threads
            MBARRIER_INIT(sb + s * 16 + 8, 512);   // empty[s]: 512 consumer threads
        }
    }
    if (t < 128) { ssum[t] = 0.0f; scan[t] = 0; }
    __syncthreads();

    if (t >= 512) {
        // ================= producers (warps 16-23), rotated W loop ===========
        int pt = t - 512;               // 0..255
        int xrow  = pt & 127;           // x row
        int xhalf = pt >> 7;            // 0/1: which 32-col half
        int sc = 0, ph = 1;

        int tile = blockIdx.x;
        int c = 0;
        float4 wv[8];

        // prologue: load first W chunk
#pragma unroll
        for (int i = 0; i < 8; i++) {
            int g = pt + i * 256;
            int row = g >> 4, k4 = (g & 15) << 2;
            int nb = tile * NTILE + row;
            wv[i] = (nb < VOUT)
                ? *(const float4*)(W + (size_t)nb * H + k4)
                : make_float4(0.f, 0.f, 0.f, 0.f);
        }

        while (tile < NT) {
            MBARRIER_WAIT_PARITY(sb + sc * 16 + 8, ph);
            uint32_t buf = sb + TILES_OFF + sc * STAGE_B;
            int k0 = c * KC;

            // x tile: pure fp16 copy via cp.async (bypasses RF)
            {
                const __half* xsrc = g_xh + xrow * H + k0 + xhalf * 32;
                uint32_t ro = buf + XH + xrow * ROWB + xhalf * 64;
#pragma unroll
                for (int j = 0; j < 4; j++)
                    CP_ASYNC16(ro + j * 16, xsrc + j * 8);
                CP_ASYNC_COMMIT();
            }

            // W: convert prefetched regs -> smem
#pragma unroll
            for (int i = 0; i < 8; i++) {
                int g = pt + i * 256;
                int row = g >> 4, k4 = (g & 15) << 2;
                unsigned h0 = (unsigned)__half_as_ushort(__float2half_rn(wv[i].x));
                unsigned h1 = (unsigned)__half_as_ushort(__float2half_rn(wv[i].y));
                unsigned h2 = (unsigned)__half_as_ushort(__float2half_rn(wv[i].z));
                unsigned h3 = (unsigned)__half_as_ushort(__float2half_rn(wv[i].w));
                unsigned a = h0 | (h1 << 16), b = h2 | (h3 << 16);
                asm volatile("st.shared.v2.b32 [%0], {%1,%2};"
                             :: "r"(buf + WH + row * ROWB + k4 * 2),
                                "r"(a), "r"(b) : "memory");
            }
            CP_ASYNC_WAIT0();
            MBARRIER_ARRIVE(sb + sc * 16);
            if (++sc == NSTAGE) { sc = 0; ph ^= 1; }

            // advance and prefetch next W chunk (overlaps next empty-wait)
            if (++c == NCH) { c = 0; tile += GRID; }
            if (tile < NT) {
                int k0n = c * KC;
#pragma unroll
                for (int i = 0; i < 8; i++) {
                    int g = pt + i * 256;
                    int row = g >> 4, k4 = (g & 15) << 2;
                    int nb = tile * NTILE + row;
                    wv[i] = (nb < VOUT)
                        ? *(const float4*)(W + (size_t)nb * H + k0n + k4)
                        : make_float4(0.f, 0.f, 0.f, 0.f);
                }
            }
        }
    } else {
        // ================= consumers (warps 0-15, 32x32 tiles) =================
        int wm = (wid >> 2) * 32;   // 0,32,64,96
        int wn = (wid & 3) * 32;    // 0,32,64,96
        int sc = 0, ph = 0;

        for (int tile = blockIdx.x; tile < NT; tile += GRID) {
            int n0 = tile * NTILE;
            float acc[2][4][4];
#pragma unroll
            for (int mi = 0; mi < 2; mi++)
#pragma unroll
                for (int ni = 0; ni < 4; ni++)
#pragma unroll
                    for (int r = 0; r < 4; r++) acc[mi][ni][r] = 0.0f;

            for (int c = 0; c < NCH; c++) {
                MBARRIER_WAIT_PARITY(sb + sc * 16, ph);
                uint32_t buf = sb + TILES_OFF + sc * STAGE_B;
#pragma unroll
                for (int k16e = 0; k16e < 4; k16e++) {
                    int k16 = k16e * 16;
                    uint32_t bh[4][2];
                    {
                        uint32_t q0, q1, q2, q3;
                        ldm4(ldm_addr(buf + WH, wn,      k16, lane), q0, q1, q2, q3);
                        bh[0][0] = q0; bh[1][0] = q1; bh[0][1] = q2; bh[1][1] = q3;
                        ldm4(ldm_addr(buf + WH, wn + 16, k16, lane), q0, q1, q2, q3);
                        bh[2][0] = q0; bh[3][0] = q1; bh[2][1] = q2; bh[3][1] = q3;
                    }
                    uint32_t ah[2][4];
#pragma unroll
                    for (int mi = 0; mi < 2; mi++)
                        ldm4(ldm_addr(buf + XH, wm + mi * 16, k16, lane),
                             ah[mi][0], ah[mi][1], ah[mi][2], ah[mi][3]);
#pragma unroll
                    for (int mi = 0; mi < 2; mi++)
#pragma unroll
                        for (int ni = 0; ni < 4; ni++)
                            mma_f16(acc[mi][ni], ah[mi], bh[ni][0], bh[ni][1]);
                }
                MBARRIER_ARRIVE(sb + sc * 16 + 8);
                if (++sc == NSTAGE) { sc = 0; ph ^= 1; }
            }

            // ---- per-tile epilogue: e = exp(acc + bias) * mask ----
#pragma unroll
            for (int mi = 0; mi < 2; mi++) {
#pragma unroll
                for (int half = 0; half < 2; half++) {
                    int m = wm + mi * 16 + (lane >> 2) + half * 8;
                    float psum = 0.0f;
                    int can = 0;
#pragma unroll
                    for (int ni = 0; ni < 4; ni++) {
                        int n = n0 + wn + ni * 8 + ((lane & 3) << 1);
                        if (n < VOUT) {
                            size_t idx = (size_t)m * VOUT + n;
                            float2 om = *(const float2*)(mask + idx);
                            float2 bv = *(const float2*)(bias + n);
                            float e0 = __expf(acc[mi][ni][half * 2 + 0] + bv.x) * om.x;
                            float e1 = __expf(acc[mi][ni][half * 2 + 1] + bv.y) * om.y;
                            *(float2*)(out_e + idx) = make_float2(e0, e1);
                            psum += e0 + e1;
                            if (om.x > 0.0f && n != 0 && g_winner[n] > 0) can = 1;
                            if (om.y > 0.0f && g_winner[n + 1] > 0) can = 1;
                        }
                    }
                    psum += __shfl_xor_sync(0xFFFFFFFFu, psum, 1);
                    psum += __shfl_xor_sync(0xFFFFFFFFu, psum, 2);
                    can |= __shfl_xor_sync(0xFFFFFFFFu, can, 1);
                    can |= __shfl_xor_sync(0xFFFFFFFFu, can, 2);
                    if ((lane & 3) == 0) {
                        atomicAdd(&ssum[m], psum);
                        if (can) scan[m] = 1;
                    }
                }
            }
            asm volatile("bar.sync 1, 512;" ::: "memory");
            if (t < 128) {
                atomicAdd(&g_expsum[t], ssum[t]);
                if (scan[t]) g_cancopy[t] = 1;
                ssum[t] = 0.0f;
                scan[t] = 0;
            }
            asm volatile("bar.sync 1, 512;" ::: "memory");
        }
    }
}

// ---------------- K4: normalize + combine + log + pog ------------------------
#define NORMSEG 25    // VOUT/25 = 2000 per segment, even
__global__ __launch_bounds__(256) void k_norm(float* __restrict__ e_gen,
                                              float* __restrict__ out_probs,
                                              float* __restrict__ out_pog) {
    int b = blockIdx.x;
    int seg = blockIdx.y;
    // compute pog gate locally (3 flops, avoids separate kernel)
    float l0 = g_pl[2 * b], l1 = g_pl[2 * b + 1];
    int can = g_cancopy[b];
    float mx = can ? fmaxf(l0, l1) : l0;
    float e0 = __expf(l0 - mx);
    float e1 = can ? __expf(l1 - mx) : 0.0f;
    float pinv = 1.0f / (e0 + e1);
    float pg = e0 * pinv, pc = e1 * pinv;
    if (seg == 0 && threadIdx.x == 0) {
        out_pog[2 * b] = pg;
        out_pog[2 * b + 1] = pc;
    }

    float inv = 1.0f / g_expsum[b];
    const float* dist = g_inpdist + (size_t)b * VIN;
    int n0 = seg * (VOUT / NORMSEG);

    for (int n = n0 + threadIdx.x * 2; n < n0 + (VOUT / NORMSEG); n += 512) {
        size_t idx = (size_t)b * VOUT + n;
        float2 e = *(const float2*)(e_gen + idx);
        int2 w = *(const int2*)(g_winner + n);
        float p0 = e.x * inv, p1 = e.y * inv;
        float ptr0 = (w.x > 0) ? dist[w.x - 1] : 0.0f;
        float ptr1 = (w.y > 0) ? dist[w.y - 1] : 0.0f;
        *(float2*)(out_probs + idx) =
            make_float2(__logf(pg * p0 + pc * ptr0), __logf(pg * p1 + pc * ptr1));
        *(float2*)(e_gen + idx) = make_float2(p0, p1);
    }
}

// ---------------- launch ------------------------------------------------------
extern "C" void kernel_launch(void* const* d_in, const int* in_sizes, int n_in,
                              void* d_out, int out_size) {
    const float* x          = (const float*)d_in[0];
    const int*   inptensor  = (const int*)  d_in[1];
    const float* attn       = (const float*)d_in[2];
    const float* out_mask   = (const float*)d_in[3];
    const float* gen_W      = (const float*)d_in[4];
    const float* gen_b      = (const float*)d_in[5];
    const float* cog_W      = (const float*)d_in[6];
    const float* cog_b      = (const float*)d_in[7];
    const int*   inp_to_act = (const int*)  d_in[8];

    float* out = (float*)d_out;
    float* o_outprobs = out;
    float* o_pog      = out + (size_t)B * VOUT;
    float* o_gen      = o_pog + 2 * B;
    float* o_attn     = o_gen + (size_t)B * VOUT;

    cudaFuncSetAttribute(k_gemm, cudaFuncAttributeMaxDynamicSharedMemorySize, SMEM_TOTAL);

    k_prep<<<128, 256>>>(x, inp_to_act);                          // 0
    k_attn<<<B, 256>>>(attn, inptensor, o_attn);                  // 1
    k_pogdot<<<B, 32>>>(x, cog_W, cog_b);                         // 2
    k_gemm<<<GRID, NTHREADS, SMEM_TOTAL>>>(gen_W, gen_b, out_mask, o_gen);  // 3 <- profiled
    k_norm<<<dim3(B, NORMSEG), 256>>>(o_gen, o_outprobs, o_pog);  // 4
}